// round 10
// baseline (speedup 1.0000x reference)
#include <cuda_runtime.h>
#include <cuda_fp16.h>
#include <cstdint>

// ---------------- problem constants ----------------
#define HID        256
#define OBS_STRIDE 54
#define SELF_OBS   18
#define NBR        6
#define BATCH_N    131072
#define TILE_B     16                    // batches per CTA iteration
#define NTILES     (BATCH_N / TILE_B)    // 8192
#define THREADS    256                   // 8 warps: warp w owns output cols [32w, 32w+32)
#define GRID_X     152
// exch[2][6][16][32] uint4, double buffered across tiles
#define SMEM_BYTES (2 * NBR * 16 * 32 * 16)   // 98304

// ==================== helpers ====================
static __device__ __forceinline__ float tanha(float x) {
    float y;
    asm("tanh.approx.f32 %0, %1;" : "=f"(y) : "f"(x));
    return y;
}
static __device__ __forceinline__ uint32_t packh2(float a, float b) {
    __half2 h = __floats2half2_rn(a, b);
    return *reinterpret_cast<uint32_t*>(&h);
}
// D[16x8] += A[16x8] * B[8x8]   (f16 in, f32 accum)
static __device__ __forceinline__ void mma_k8(float& d0, float& d1, float& d2, float& d3,
                                              uint32_t a0, uint32_t a1, uint32_t b0) {
    asm volatile("mma.sync.aligned.m16n8k8.row.col.f32.f16.f16.f32 "
                 "{%0,%1,%2,%3}, {%4,%5}, {%6}, {%0,%1,%2,%3};"
                 : "+f"(d0), "+f"(d1), "+f"(d2), "+f"(d3)
                 : "r"(a0), "r"(a1), "r"(b0));
}
// D[16x8] += A[16x16] * B[16x8]
static __device__ __forceinline__ void mma_k16(float* d,
                                               uint32_t a0, uint32_t a1, uint32_t a2, uint32_t a3,
                                               uint32_t b0, uint32_t b1) {
    asm volatile("mma.sync.aligned.m16n8k16.row.col.f32.f16.f16.f32 "
                 "{%0,%1,%2,%3}, {%4,%5,%6,%7}, {%8,%9}, {%0,%1,%2,%3};"
                 : "+f"(d[0]), "+f"(d[1]), "+f"(d[2]), "+f"(d[3])
                 : "r"(a0), "r"(a1), "r"(a2), "r"(a3), "r"(b0), "r"(b1));
}

// ==================== kernel ====================
__global__ void __launch_bounds__(THREADS, 1)
deepsets_kernel(const float* __restrict__ obs,
                const float* __restrict__ W1,
                const float* __restrict__ b1,
                const float* __restrict__ W2,
                const float* __restrict__ b2,
                float* __restrict__ out)
{
    // A-fragment exchange: [buf][nb][k-chunk][lane]; chunk c produced by warp c>>1.
    extern __shared__ uint4 exch[];

    const int tid  = threadIdx.x;
    const int w    = tid >> 5;      // warp id = 32-col output n-slice, produces chunks 2w,2w+1
    const int lane = tid & 31;
    const int gid  = lane >> 2;     // fragment row group (0..7)
    const int tig  = lane & 3;      // thread-in-group
    const int n0   = w * 32;

    // ---- resident W1 B-fragments + bias fragments ----
    // warp w's produced chunks cover hidden n8-tiles tt = 4w..4w+3; its OUTPUT cols
    // are also tiles 4w..4w+3 — so b1v/b2v share indexing.
    uint32_t w1b[4];
    float2 b1v[4], b2v[4];
    #pragma unroll
    for (int j = 0; j < 4; j++) {
        int tt = 4 * w + j;
        int n  = tt * 8 + gid;
        int c  = tt * 8 + 2 * tig;
        w1b[j] = (tig < 3) ? packh2(W1[2 * tig * HID + n], W1[(2 * tig + 1) * HID + n]) : 0u;
        b1v[j] = make_float2(b1[c], b1[c + 1]);
        b2v[j] = make_float2(b2[c], b2[c + 1]);
    }

    // ---- resident W2 B-fragments: warp w holds W2[:, n0..n0+31] (128 regs) ----
    uint32_t blo[16][4], bhi[16][4];
    #pragma unroll
    for (int c = 0; c < 16; c++) {
        #pragma unroll
        for (int t = 0; t < 4; t++) {
            int n = n0 + t * 8 + gid;
            int k = c * 16 + 2 * tig;
            blo[c][t] = packh2(W2[k * HID + n],       W2[(k + 1) * HID + n]);
            bhi[c][t] = packh2(W2[(k + 8) * HID + n], W2[(k + 9) * HID + n]);
        }
    }

    const float inv6 = 1.0f / 6.0f;

    // prefetch+pack the 6 neighbors' x-fragments of tile at batch base b0 (pure regs)
    auto xfetch = [&](long b0, uint32_t (*xp)[2]) {
        #pragma unroll
        for (int nb = 0; nb < NBR; nb++) {
            xp[nb][0] = 0u; xp[nb][1] = 0u;
            if (tig < 3) {   // k = 2*tig, 2*tig+1 < 6 ; tig==3 is the zero pad
                const float* p = obs + (b0 + gid) * OBS_STRIDE + SELF_OBS + nb * 6 + 2 * tig;
                float2 v0 = *reinterpret_cast<const float2*>(p);
                float2 v1 = *reinterpret_cast<const float2*>(p + 8 * OBS_STRIDE);
                xp[nb][0] = packh2(v0.x, v0.y);
                xp[nb][1] = packh2(v1.x, v1.y);
            }
        }
    };

    // layer-1 for neighbor nb from prefetched x regs -> chunks 2w, 2w+1 of exch[buf]
    auto layer1 = [&](int nb, const uint32_t (*xp)[2], int buf) {
        #pragma unroll
        for (int cc = 0; cc < 2; cc++) {
            uint4 pk;
            uint32_t* pkr = reinterpret_cast<uint32_t*>(&pk);
            #pragma unroll
            for (int jj = 0; jj < 2; jj++) {
                int j = cc * 2 + jj;
                float d0 = 0.f, d1 = 0.f, d2 = 0.f, d3 = 0.f;
                mma_k8(d0, d1, d2, d3, xp[nb][0], xp[nb][1], w1b[j]);
                pkr[jj * 2 + 0] = packh2(tanha(d0 + b1v[j].x), tanha(d1 + b1v[j].y));
                pkr[jj * 2 + 1] = packh2(tanha(d2 + b1v[j].x), tanha(d3 + b1v[j].y));
            }
            exch[((buf * NBR + nb) * 16 + 2 * w + cc) * 32 + lane] = pk;
        }
    };

    // ---- prologue: x + A-fragments for this CTA's first tile ----
    uint32_t xp[NBR][2];
    {
        long b0 = (long)blockIdx.x * TILE_B;
        xfetch(b0, xp);
        #pragma unroll
        for (int nb = 0; nb < NBR; nb++) layer1(nb, xp, 0);
    }
    __syncthreads();

    int buf = 0;
    for (int tile = blockIdx.x; tile < NTILES; tile += gridDim.x) {
        const long b0     = (long)tile * TILE_B;
        const int  ntile  = tile + gridDim.x;
        const bool has_nx = (ntile < NTILES);

        // issue next tile's 12 LDGs NOW — consumed ~6K cycles later, so layer1
        // below is pure compute (no long-scoreboard stalls).
        if (has_nx) xfetch((long)ntile * TILE_B, xp);

        float acc[4][4];
        #pragma unroll
        for (int t = 0; t < 4; t++)
            #pragma unroll
            for (int i = 0; i < 4; i++) acc[t][i] = 0.0f;

        float Dp[4][4];
        // interleaved: produce A(next tile) while consuming A(this tile);
        // epilogue of nb-1 deferred into nb's HMMA burst (MUFU under tensor).
        #pragma unroll
        for (int nb = 0; nb < NBR; nb++) {
            if (has_nx) layer1(nb, xp, buf ^ 1);      // MUFU + STS stream (no gmem)

            // tensor + LDS stream: D[16x32] = h1[16x256] @ W2[:, n0..n0+31]
            float D[4][4];
            #pragma unroll
            for (int t = 0; t < 4; t++)
                #pragma unroll
                for (int i = 0; i < 4; i++) D[t][i] = 0.0f;

            const uint4* ap = &exch[((buf * NBR + nb) * 16) * 32 + lane];
            #pragma unroll
            for (int c = 0; c < 16; c++) {
                uint4 a = ap[c * 32];
                mma_k16(D[0], a.x, a.y, a.z, a.w, blo[c][0], bhi[c][0]);
                mma_k16(D[1], a.x, a.y, a.z, a.w, blo[c][1], bhi[c][1]);
                mma_k16(D[2], a.x, a.y, a.z, a.w, blo[c][2], bhi[c][2]);
                mma_k16(D[3], a.x, a.y, a.z, a.w, blo[c][3], bhi[c][3]);
            }

            // deferred epilogue of previous neighbor (independent of this burst)
            if (nb > 0) {
                #pragma unroll
                for (int t = 0; t < 4; t++) {
                    acc[t][0] += tanha(Dp[t][0] + b2v[t].x);
                    acc[t][1] += tanha(Dp[t][1] + b2v[t].y);
                    acc[t][2] += tanha(Dp[t][2] + b2v[t].x);
                    acc[t][3] += tanha(Dp[t][3] + b2v[t].y);
                }
            }
            #pragma unroll
            for (int t = 0; t < 4; t++)
                #pragma unroll
                for (int i = 0; i < 4; i++) Dp[t][i] = D[t][i];   // register rename
        }
        // last neighbor's epilogue
        #pragma unroll
        for (int t = 0; t < 4; t++) {
            acc[t][0] += tanha(Dp[t][0] + b2v[t].x);
            acc[t][1] += tanha(Dp[t][1] + b2v[t].y);
            acc[t][2] += tanha(Dp[t][2] + b2v[t].x);
            acc[t][3] += tanha(Dp[t][3] + b2v[t].y);
        }

        // ---- mean over neighbors, write out ----
        #pragma unroll
        for (int t = 0; t < 4; t++) {
            int col = n0 + t * 8 + 2 * tig;
            float2 v0 = make_float2(acc[t][0] * inv6, acc[t][1] * inv6);
            float2 v1 = make_float2(acc[t][2] * inv6, acc[t][3] * inv6);
            *reinterpret_cast<float2*>(&out[(b0 + gid)     * HID + col]) = v0;
            *reinterpret_cast<float2*>(&out[(b0 + gid + 8) * HID + col]) = v1;
        }

        __syncthreads();  // exch[buf] reads done before its rewrite next tile;
                          // exch[buf^1] writes visible before next tile's reads
        buf ^= 1;
    }
}

// ==================== launch ====================
extern "C" void kernel_launch(void* const* d_in, const int* in_sizes, int n_in,
                              void* d_out, int out_size) {
    // inputs: self_obs(131072*18), obs(131072*54), W1(6*256), b1(256), W2(256*256), b2(256)
    const float* obs = nullptr;
    const float* W1  = nullptr;
    const float* b1  = nullptr;
    const float* W2  = nullptr;
    const float* b2  = nullptr;
    for (int i = 0; i < n_in; i++) {
        int sz = in_sizes[i];
        if (sz == BATCH_N * OBS_STRIDE)  obs = (const float*)d_in[i];
        else if (sz == 6 * HID)          W1  = (const float*)d_in[i];
        else if (sz == HID * HID)        W2  = (const float*)d_in[i];
        else if (sz == HID) {
            if (!b1) b1 = (const float*)d_in[i];
            else if (!b2) b2 = (const float*)d_in[i];
        }
    }
    float* out = (float*)d_out;

    cudaFuncSetAttribute(deepsets_kernel,
                         cudaFuncAttributeMaxDynamicSharedMemorySize, SMEM_BYTES);
    deepsets_kernel<<<GRID_X, THREADS, SMEM_BYTES>>>(obs, W1, b1, W2, b2, out);
}

// round 11
// speedup vs baseline: 1.1528x; 1.1528x over previous
#include <cuda_runtime.h>
#include <cuda_fp16.h>
#include <cstdint>

// ---------------- problem constants ----------------
#define HID        256
#define OBS_STRIDE 54
#define SELF_OBS   18
#define NBR        6
#define BATCH_N    131072
#define TILE_B     16                    // batches per CTA iteration
#define NTILES     (BATCH_N / TILE_B)    // 8192
#define THREADS    512                   // 16 warps: warp w owns hidden/output cols [16w, 16w+16)
#define GRID_X     152

// smem: exch[2][6][16][32] uint4 (98304 B) then xs[2][16][42] float (5376 B)
#define EXCH_BYTES (2 * NBR * 16 * 32 * 16)
#define XS_STRIDE  42
#define XS_BYTES   (2 * TILE_B * XS_STRIDE * 4)
#define SMEM_BYTES (EXCH_BYTES + XS_BYTES)

// ==================== helpers ====================
static __device__ __forceinline__ float tanha(float x) {
    float y;
    asm("tanh.approx.f32 %0, %1;" : "=f"(y) : "f"(x));
    return y;
}
static __device__ __forceinline__ uint32_t packh2(float a, float b) {
    __half2 h = __floats2half2_rn(a, b);
    return *reinterpret_cast<uint32_t*>(&h);
}
// D[16x8] += A[16x8] * B[8x8]   (f16 in, f32 accum)
static __device__ __forceinline__ void mma_k8(float& d0, float& d1, float& d2, float& d3,
                                              uint32_t a0, uint32_t a1, uint32_t b0) {
    asm volatile("mma.sync.aligned.m16n8k8.row.col.f32.f16.f16.f32 "
                 "{%0,%1,%2,%3}, {%4,%5}, {%6}, {%0,%1,%2,%3};"
                 : "+f"(d0), "+f"(d1), "+f"(d2), "+f"(d3)
                 : "r"(a0), "r"(a1), "r"(b0));
}
// D[16x8] += A[16x16] * B[16x8]
static __device__ __forceinline__ void mma_k16(float* d,
                                               uint32_t a0, uint32_t a1, uint32_t a2, uint32_t a3,
                                               uint32_t b0, uint32_t b1) {
    asm volatile("mma.sync.aligned.m16n8k16.row.col.f32.f16.f16.f32 "
                 "{%0,%1,%2,%3}, {%4,%5,%6,%7}, {%8,%9}, {%0,%1,%2,%3};"
                 : "+f"(d[0]), "+f"(d[1]), "+f"(d[2]), "+f"(d[3])
                 : "r"(a0), "r"(a1), "r"(a2), "r"(a3), "r"(b0), "r"(b1));
}

// ==================== kernel ====================
__global__ void __launch_bounds__(THREADS, 1)
deepsets_kernel(const float* __restrict__ obs,
                const float* __restrict__ W1,
                const float* __restrict__ b1,
                const float* __restrict__ W2,
                const float* __restrict__ b2,
                float* __restrict__ out)
{
    extern __shared__ char smem[];
    // A-fragment exchange: [buf][nb][k-chunk][lane]; chunk c produced by warp c.
    uint4* exch = reinterpret_cast<uint4*>(smem);
    // staged neighbor-obs: xs[p][row][42], rows padded for conflict-free strided reads
    float* xsf = reinterpret_cast<float*>(smem + EXCH_BYTES);

    const int tid  = threadIdx.x;
    const int w    = tid >> 5;      // warp id = 16-col hidden/output n-slice
    const int lane = tid & 31;
    const int gid  = lane >> 2;     // fragment row group (0..7)
    const int tig  = lane & 3;      // thread-in-group
    const int n0   = w * 16;

    // ---- resident W1 B-fragments + bias fragments ----
    uint32_t w1b[2];
    float2 b1v[2], b2v[2];
    #pragma unroll
    for (int j = 0; j < 2; j++) {
        int tt = 2 * w + j;                 // global hidden n8-tile
        int n  = tt * 8 + gid;
        int c  = tt * 8 + 2 * tig;
        w1b[j] = (tig < 3) ? packh2(W1[2 * tig * HID + n], W1[(2 * tig + 1) * HID + n]) : 0u;
        b1v[j] = make_float2(b1[c], b1[c + 1]);
        b2v[j] = make_float2(b2[c], b2[c + 1]);
    }

    // ---- resident W2 B-fragments: warp w holds W2[:, n0..n0+15] (64 regs) ----
    uint32_t blo[16][2], bhi[16][2];
    #pragma unroll
    for (int c = 0; c < 16; c++) {
        #pragma unroll
        for (int t = 0; t < 2; t++) {
            int n = n0 + t * 8 + gid;
            int k = c * 16 + 2 * tig;
            blo[c][t] = packh2(W2[k * HID + n],       W2[(k + 1) * HID + n]);
            bhi[c][t] = packh2(W2[(k + 8) * HID + n], W2[(k + 9) * HID + n]);
        }
    }

    const float inv6 = 1.0f / 6.0f;

    // stage the 16x36 neighbor-obs block of tile at batch base b0 into xs[p] (coalesced)
    auto xstage = [&](long b0, int p) {
        #pragma unroll
        for (int i = tid; i < TILE_B * 36; i += THREADS) {
            int r = i / 36, c = i % 36;
            xsf[(p * TILE_B + r) * XS_STRIDE + c] = obs[(b0 + r) * OBS_STRIDE + SELF_OBS + c];
        }
    };

    // layer-1 for neighbor nb of the tile staged in xs[p] -> exch[buf] (reads smem only)
    auto layer1 = [&](int nb, int p, int buf) {
        uint32_t xa0 = 0u, xa1 = 0u;
        if (tig < 3) {
            const float* q = &xsf[(p * TILE_B + gid) * XS_STRIDE + nb * 6 + 2 * tig];
            float2 v0 = *reinterpret_cast<const float2*>(q);
            float2 v1 = *reinterpret_cast<const float2*>(q + 8 * XS_STRIDE);
            xa0 = packh2(v0.x, v0.y);
            xa1 = packh2(v1.x, v1.y);
        }
        uint4 pk;
        uint32_t* pkr = reinterpret_cast<uint32_t*>(&pk);
        #pragma unroll
        for (int j = 0; j < 2; j++) {
            float d0 = 0.f, d1 = 0.f, d2 = 0.f, d3 = 0.f;
            mma_k8(d0, d1, d2, d3, xa0, xa1, w1b[j]);
            pkr[j * 2 + 0] = packh2(tanha(d0 + b1v[j].x), tanha(d1 + b1v[j].y));
            pkr[j * 2 + 1] = packh2(tanha(d2 + b1v[j].x), tanha(d3 + b1v[j].y));
        }
        exch[((buf * NBR + nb) * 16 + w) * 32 + lane] = pk;
    };

    // ---- prologue: stage x(T0) and x(T1); build A(T0) ----
    {
        long t0 = (long)blockIdx.x;
        xstage(t0 * TILE_B, 0);
        if (t0 + GRID_X < NTILES) xstage((t0 + GRID_X) * TILE_B, 1);
        __syncthreads();
        #pragma unroll
        for (int nb = 0; nb < NBR; nb++) layer1(nb, 0, 0);
    }
    __syncthreads();

    int buf = 0;   // exch/xs parity: this tile consumes exch[buf]; layer1(next) reads xs[buf^1]
    for (int tile = blockIdx.x; tile < NTILES; tile += gridDim.x) {
        const long b0     = (long)tile * TILE_B;
        const bool has_nx = (tile + gridDim.x < NTILES);
        const bool has_n2 = (tile + 2 * gridDim.x < NTILES);

        // stage x(tile+2) into xs[buf] (its old contents, x(tile), were last read
        // during the previous tile's layer1 — separated by the loop barrier).
        if (has_n2) xstage((long)(tile + 2 * gridDim.x) * TILE_B, buf);

        float acc[2][4];
        #pragma unroll
        for (int t = 0; t < 2; t++)
            #pragma unroll
            for (int i = 0; i < 4; i++) acc[t][i] = 0.0f;

        float Dp[2][4];
        // interleaved: produce A(next tile) while consuming A(this tile);
        // epilogue of nb-1 deferred into nb's HMMA burst (MUFU under tensor).
        #pragma unroll
        for (int nb = 0; nb < NBR; nb++) {
            if (has_nx) layer1(nb, buf ^ 1, buf ^ 1);   // MUFU + LDS + STS stream

            // tensor + LDS stream: D[16x16] = h1[16x256] @ W2[:, n0..n0+15]
            float D[2][4];
            #pragma unroll
            for (int t = 0; t < 2; t++)
                #pragma unroll
                for (int i = 0; i < 4; i++) D[t][i] = 0.0f;

            const uint4* ap = &exch[((buf * NBR + nb) * 16) * 32 + lane];
            #pragma unroll
            for (int c = 0; c < 16; c++) {
                uint4 a = ap[c * 32];
                mma_k16(D[0], a.x, a.y, a.z, a.w, blo[c][0], bhi[c][0]);
                mma_k16(D[1], a.x, a.y, a.z, a.w, blo[c][1], bhi[c][1]);
            }

            // deferred epilogue of previous neighbor (independent of this burst)
            if (nb > 0) {
                #pragma unroll
                for (int t = 0; t < 2; t++) {
                    acc[t][0] += tanha(Dp[t][0] + b2v[t].x);
                    acc[t][1] += tanha(Dp[t][1] + b2v[t].y);
                    acc[t][2] += tanha(Dp[t][2] + b2v[t].x);
                    acc[t][3] += tanha(Dp[t][3] + b2v[t].y);
                }
            }
            #pragma unroll
            for (int t = 0; t < 2; t++)
                #pragma unroll
                for (int i = 0; i < 4; i++) Dp[t][i] = D[t][i];   // register rename
        }
        // last neighbor's epilogue
        #pragma unroll
        for (int t = 0; t < 2; t++) {
            acc[t][0] += tanha(Dp[t][0] + b2v[t].x);
            acc[t][1] += tanha(Dp[t][1] + b2v[t].y);
            acc[t][2] += tanha(Dp[t][2] + b2v[t].x);
            acc[t][3] += tanha(Dp[t][3] + b2v[t].y);
        }

        // ---- mean over neighbors, write out ----
        #pragma unroll
        for (int t = 0; t < 2; t++) {
            int col = n0 + t * 8 + 2 * tig;
            float2 v0 = make_float2(acc[t][0] * inv6, acc[t][1] * inv6);
            float2 v1 = make_float2(acc[t][2] * inv6, acc[t][3] * inv6);
            *reinterpret_cast<float2*>(&out[(b0 + gid)     * HID + col]) = v0;
            *reinterpret_cast<float2*>(&out[(b0 + gid + 8) * HID + col]) = v1;
        }

        __syncthreads();  // orders: exch[buf] reads before rewrite; exch[buf^1] & xs[buf]
                          // writes visible before next tile's reads
        buf ^= 1;
    }
}

// ==================== launch ====================
extern "C" void kernel_launch(void* const* d_in, const int* in_sizes, int n_in,
                              void* d_out, int out_size) {
    // inputs: self_obs(131072*18), obs(131072*54), W1(6*256), b1(256), W2(256*256), b2(256)
    const float* obs = nullptr;
    const float* W1  = nullptr;
    const float* b1  = nullptr;
    const float* W2  = nullptr;
    const float* b2  = nullptr;
    for (int i = 0; i < n_in; i++) {
        int sz = in_sizes[i];
        if (sz == BATCH_N * OBS_STRIDE)  obs = (const float*)d_in[i];
        else if (sz == 6 * HID)          W1  = (const float*)d_in[i];
        else if (sz == HID * HID)        W2  = (const float*)d_in[i];
        else if (sz == HID) {
            if (!b1) b1 = (const float*)d_in[i];
            else if (!b2) b2 = (const float*)d_in[i];
        }
    }
    float* out = (float*)d_out;

    cudaFuncSetAttribute(deepsets_kernel,
                         cudaFuncAttributeMaxDynamicSharedMemorySize, SMEM_BYTES);
    deepsets_kernel<<<GRID_X, THREADS, SMEM_BYTES>>>(obs, W1, b1, W2, b2, out);
}

// round 12
// speedup vs baseline: 1.1719x; 1.0166x over previous
#include <cuda_runtime.h>
#include <cuda_fp16.h>
#include <cstdint>

// ---------------- problem constants ----------------
#define HID        256
#define OBS_STRIDE 54
#define SELF_OBS   18
#define NBR        6
#define BATCH_N    131072
#define TILE_B     16                    // batches per CTA iteration
#define NTILES     (BATCH_N / TILE_B)    // 8192
#define THREADS    512                   // 16 warps: warp w owns hidden/output cols [16w, 16w+16)
#define GRID_X     152

// smem: exch[2][6][16][32] uint4 (98304 B) then xs[2][16][42] float (5376 B)
#define EXCH_BYTES (2 * NBR * 16 * 32 * 16)
#define XS_STRIDE  42
#define XS_BYTES   (2 * TILE_B * XS_STRIDE * 4)
#define SMEM_BYTES (EXCH_BYTES + XS_BYTES)

// ==================== helpers ====================
static __device__ __forceinline__ float tanha(float x) {
    float y;
    asm("tanh.approx.f32 %0, %1;" : "=f"(y) : "f"(x));
    return y;
}
static __device__ __forceinline__ uint32_t packh2(float a, float b) {
    __half2 h = __floats2half2_rn(a, b);
    return *reinterpret_cast<uint32_t*>(&h);
}
// D[16x8] += A[16x8] * B[8x8]   (f16 in, f32 accum)
static __device__ __forceinline__ void mma_k8(float& d0, float& d1, float& d2, float& d3,
                                              uint32_t a0, uint32_t a1, uint32_t b0) {
    asm volatile("mma.sync.aligned.m16n8k8.row.col.f32.f16.f16.f32 "
                 "{%0,%1,%2,%3}, {%4,%5}, {%6}, {%0,%1,%2,%3};"
                 : "+f"(d0), "+f"(d1), "+f"(d2), "+f"(d3)
                 : "r"(a0), "r"(a1), "r"(b0));
}
// D[16x8] += A[16x16] * B[16x8]
static __device__ __forceinline__ void mma_k16(float* d,
                                               uint32_t a0, uint32_t a1, uint32_t a2, uint32_t a3,
                                               uint32_t b0, uint32_t b1) {
    asm volatile("mma.sync.aligned.m16n8k16.row.col.f32.f16.f16.f32 "
                 "{%0,%1,%2,%3}, {%4,%5,%6,%7}, {%8,%9}, {%0,%1,%2,%3};"
                 : "+f"(d[0]), "+f"(d[1]), "+f"(d[2]), "+f"(d[3])
                 : "r"(a0), "r"(a1), "r"(a2), "r"(a3), "r"(b0), "r"(b1));
}

// ==================== kernel ====================
__global__ void __launch_bounds__(THREADS, 1)
deepsets_kernel(const float* __restrict__ obs,
                const float* __restrict__ W1,
                const float* __restrict__ b1,
                const float* __restrict__ W2,
                const float* __restrict__ b2,
                float* __restrict__ out)
{
    extern __shared__ char smem[];
    // A-fragment exchange: [buf][nb][k-chunk][lane]; chunk c produced by warp c.
    uint4* exch = reinterpret_cast<uint4*>(smem);
    // staged neighbor-obs: xs[p][row][42], rows padded for conflict-free strided reads
    float* xsf = reinterpret_cast<float*>(smem + EXCH_BYTES);

    const int tid  = threadIdx.x;
    const int w    = tid >> 5;      // warp id = 16-col hidden/output n-slice
    const int lane = tid & 31;
    const int gid  = lane >> 2;     // fragment row group (0..7)
    const int tig  = lane & 3;      // thread-in-group
    const int n0   = w * 16;
    const bool wodd = (w & 1);      // phase-stagger parity

    // ---- resident W1 B-fragments + bias fragments ----
    uint32_t w1b[2];
    float2 b1v[2], b2v[2];
    #pragma unroll
    for (int j = 0; j < 2; j++) {
        int tt = 2 * w + j;                 // global hidden n8-tile
        int n  = tt * 8 + gid;
        int c  = tt * 8 + 2 * tig;
        w1b[j] = (tig < 3) ? packh2(W1[2 * tig * HID + n], W1[(2 * tig + 1) * HID + n]) : 0u;
        b1v[j] = make_float2(b1[c], b1[c + 1]);
        b2v[j] = make_float2(b2[c], b2[c + 1]);
    }

    // ---- resident W2 B-fragments: warp w holds W2[:, n0..n0+15] (64 regs) ----
    uint32_t blo[16][2], bhi[16][2];
    #pragma unroll
    for (int c = 0; c < 16; c++) {
        #pragma unroll
        for (int t = 0; t < 2; t++) {
            int n = n0 + t * 8 + gid;
            int k = c * 16 + 2 * tig;
            blo[c][t] = packh2(W2[k * HID + n],       W2[(k + 1) * HID + n]);
            bhi[c][t] = packh2(W2[(k + 8) * HID + n], W2[(k + 9) * HID + n]);
        }
    }

    const float inv6 = 1.0f / 6.0f;

    // stage the 16x36 neighbor-obs block of tile at batch base b0 into xs[p] (coalesced)
    auto xstage = [&](long b0, int p) {
        #pragma unroll
        for (int i = tid; i < TILE_B * 36; i += THREADS) {
            int r = i / 36, c = i % 36;
            xsf[(p * TILE_B + r) * XS_STRIDE + c] = obs[(b0 + r) * OBS_STRIDE + SELF_OBS + c];
        }
    };

    // layer-1 for neighbor nb of the tile staged in xs[p] -> exch[buf] (reads smem only)
    auto layer1 = [&](int nb, int p, int buf) {
        uint32_t xa0 = 0u, xa1 = 0u;
        if (tig < 3) {
            const float* q = &xsf[(p * TILE_B + gid) * XS_STRIDE + nb * 6 + 2 * tig];
            float2 v0 = *reinterpret_cast<const float2*>(q);
            float2 v1 = *reinterpret_cast<const float2*>(q + 8 * XS_STRIDE);
            xa0 = packh2(v0.x, v0.y);
            xa1 = packh2(v1.x, v1.y);
        }
        uint4 pk;
        uint32_t* pkr = reinterpret_cast<uint32_t*>(&pk);
        #pragma unroll
        for (int j = 0; j < 2; j++) {
            float d0 = 0.f, d1 = 0.f, d2 = 0.f, d3 = 0.f;
            mma_k8(d0, d1, d2, d3, xa0, xa1, w1b[j]);
            pkr[j * 2 + 0] = packh2(tanha(d0 + b1v[j].x), tanha(d1 + b1v[j].y));
            pkr[j * 2 + 1] = packh2(tanha(d2 + b1v[j].x), tanha(d3 + b1v[j].y));
        }
        exch[((buf * NBR + nb) * 16 + w) * 32 + lane] = pk;
    };

    // ---- prologue: stage x(T0) and x(T1); build A(T0) ----
    {
        long t0 = (long)blockIdx.x;
        xstage(t0 * TILE_B, 0);
        if (t0 + GRID_X < NTILES) xstage((t0 + GRID_X) * TILE_B, 1);
        __syncthreads();
        #pragma unroll
        for (int nb = 0; nb < NBR; nb++) layer1(nb, 0, 0);
    }
    __syncthreads();

    int buf = 0;   // exch/xs parity: this tile consumes exch[buf]; layer1(next) reads xs[buf^1]
    for (int tile = blockIdx.x; tile < NTILES; tile += gridDim.x) {
        const long b0     = (long)tile * TILE_B;
        const bool has_nx = (tile + gridDim.x < NTILES);
        const bool has_n2 = (tile + 2 * gridDim.x < NTILES);

        // stage x(tile+2) into xs[buf] (its old contents, x(tile), were last read
        // during the previous tile's layer1 — separated by the loop barrier).
        if (has_n2) xstage((long)(tile + 2 * gridDim.x) * TILE_B, buf);

        float acc[2][4];
        #pragma unroll
        for (int t = 0; t < 2; t++)
            #pragma unroll
            for (int i = 0; i < 4; i++) acc[t][i] = 0.0f;

        float Dp[2][4];
        // burst: HMMA over exch[buf][nb] + deferred epilogue of previous neighbor.
        auto burst = [&](int nb) {
            float D[2][4];
            #pragma unroll
            for (int t = 0; t < 2; t++)
                #pragma unroll
                for (int i = 0; i < 4; i++) D[t][i] = 0.0f;

            const uint4* ap = &exch[((buf * NBR + nb) * 16) * 32 + lane];
            #pragma unroll
            for (int c = 0; c < 16; c++) {
                uint4 a = ap[c * 32];
                mma_k16(D[0], a.x, a.y, a.z, a.w, blo[c][0], bhi[c][0]);
                mma_k16(D[1], a.x, a.y, a.z, a.w, blo[c][1], bhi[c][1]);
            }
            if (nb > 0) {   // deferred epilogue of previous neighbor (independent MUFUs)
                #pragma unroll
                for (int t = 0; t < 2; t++) {
                    acc[t][0] += tanha(Dp[t][0] + b2v[t].x);
                    acc[t][1] += tanha(Dp[t][1] + b2v[t].y);
                    acc[t][2] += tanha(Dp[t][2] + b2v[t].x);
                    acc[t][3] += tanha(Dp[t][3] + b2v[t].y);
                }
            }
            #pragma unroll
            for (int t = 0; t < 2; t++)
                #pragma unroll
                for (int i = 0; i < 4; i++) Dp[t][i] = D[t][i];   // register rename
        };

        // Phase-staggered interleave: even warps run (layer1 -> burst), odd warps
        // (burst -> layer1). Legal: burst(nb) reads exch[buf] (written last tile),
        // layer1(nb) writes exch[buf^1] — no intra-tile ordering between them.
        // Decorrelates MUFU vs LDS+HMMA demand across the 4 warps of each SMSP.
        #pragma unroll
        for (int nb = 0; nb < NBR; nb++) {
            if (wodd) {
                burst(nb);
                if (has_nx) layer1(nb, buf ^ 1, buf ^ 1);
            } else {
                if (has_nx) layer1(nb, buf ^ 1, buf ^ 1);
                burst(nb);
            }
        }
        // last neighbor's epilogue
        #pragma unroll
        for (int t = 0; t < 2; t++) {
            acc[t][0] += tanha(Dp[t][0] + b2v[t].x);
            acc[t][1] += tanha(Dp[t][1] + b2v[t].y);
            acc[t][2] += tanha(Dp[t][2] + b2v[t].x);
            acc[t][3] += tanha(Dp[t][3] + b2v[t].y);
        }

        // ---- mean over neighbors, write out ----
        #pragma unroll
        for (int t = 0; t < 2; t++) {
            int col = n0 + t * 8 + 2 * tig;
            float2 v0 = make_float2(acc[t][0] * inv6, acc[t][1] * inv6);
            float2 v1 = make_float2(acc[t][2] * inv6, acc[t][3] * inv6);
            *reinterpret_cast<float2*>(&out[(b0 + gid)     * HID + col]) = v0;
            *reinterpret_cast<float2*>(&out[(b0 + gid + 8) * HID + col]) = v1;
        }

        __syncthreads();  // orders: exch[buf] reads before rewrite; exch[buf^1] & xs[buf]
                          // writes visible before next tile's reads
        buf ^= 1;
    }
}

// ==================== launch ====================
extern "C" void kernel_launch(void* const* d_in, const int* in_sizes, int n_in,
                              void* d_out, int out_size) {
    // inputs: self_obs(131072*18), obs(131072*54), W1(6*256), b1(256), W2(256*256), b2(256)
    const float* obs = nullptr;
    const float* W1  = nullptr;
    const float* b1  = nullptr;
    const float* W2  = nullptr;
    const float* b2  = nullptr;
    for (int i = 0; i < n_in; i++) {
        int sz = in_sizes[i];
        if (sz == BATCH_N * OBS_STRIDE)  obs = (const float*)d_in[i];
        else if (sz == 6 * HID)          W1  = (const float*)d_in[i];
        else if (sz == HID * HID)        W2  = (const float*)d_in[i];
        else if (sz == HID) {
            if (!b1) b1 = (const float*)d_in[i];
            else if (!b2) b2 = (const float*)d_in[i];
        }
    }
    float* out = (float*)d_out;

    cudaFuncSetAttribute(deepsets_kernel,
                         cudaFuncAttributeMaxDynamicSharedMemorySize, SMEM_BYTES);
    deepsets_kernel<<<GRID_X, THREADS, SMEM_BYTES>>>(obs, W1, b1, W2, b2, out);
}